// round 2
// baseline (speedup 1.0000x reference)
#include <cuda_runtime.h>
#include <math.h>

#define NV   8192
#define DV   256
#define NEGF (-1000000000.0f)

// Scratch (allocation-free rule: __device__ globals)
__device__ float g_Wh[NV * DV];       // 8 MB, L2-resident during k_attn
__device__ float g_f[NV];
__device__ float g_m[NV];
__device__ float g_is[NV];            // 1/sum
__device__ float g_elu_scratch[NV * DV]; // fallback if d_out holds alpha only

__device__ __forceinline__ float lk(float x) { return x > 0.f ? x : 0.2f * x; }
__device__ __forceinline__ float elu_f(float x) { return x > 0.f ? x : expm1f(x); }

// ---------------------------------------------------------------------------
// Kernel 1: Wh = h @ W   (M=8192, N=256, K=256), 64-row x 256-col block tile
// ---------------------------------------------------------------------------
__global__ __launch_bounds__(256) void k_gemm_wh(const float* __restrict__ h,
                                                 const float* __restrict__ W) {
    __shared__ float hS[64][33];     // K-step 32, pad 33 -> conflict-free reads
    __shared__ float wS[32][256];
    const int tid = threadIdx.x;
    const int tx = tid & 15, ty = tid >> 4;
    const int r0 = blockIdx.x * 64;

    float acc[4][4][4];
#pragma unroll
    for (int v = 0; v < 4; v++)
#pragma unroll
        for (int g = 0; g < 4; g++)
#pragma unroll
            for (int u = 0; u < 4; u++) acc[v][g][u] = 0.f;

    for (int kb = 0; kb < DV; kb += 32) {
        // h tile: 64x32 = 512 float4
#pragma unroll
        for (int q = 0; q < 2; q++) {
            int lin = q * 256 + tid;
            int r = lin >> 3, c4 = (lin & 7) * 4;
            float4 v = *(const float4*)&h[(size_t)(r0 + r) * DV + kb + c4];
            hS[r][c4] = v.x; hS[r][c4 + 1] = v.y; hS[r][c4 + 2] = v.z; hS[r][c4 + 3] = v.w;
        }
        // W tile: 32x256 = 2048 float4
#pragma unroll
        for (int q = 0; q < 8; q++) {
            int lin = q * 256 + tid;
            int k = lin >> 6, c4 = (lin & 63) * 4;
            *(float4*)&wS[k][c4] = *(const float4*)&W[(size_t)(kb + k) * DV + c4];
        }
        __syncthreads();
#pragma unroll 8
        for (int k = 0; k < 32; k++) {
            float av[4];
#pragma unroll
            for (int v = 0; v < 4; v++) av[v] = hS[ty * 4 + v][k];
#pragma unroll
            for (int g = 0; g < 4; g++) {
                float4 w = *(float4*)&wS[k][g * 64 + tx * 4];
#pragma unroll
                for (int v = 0; v < 4; v++) {
                    acc[v][g][0] += av[v] * w.x;
                    acc[v][g][1] += av[v] * w.y;
                    acc[v][g][2] += av[v] * w.z;
                    acc[v][g][3] += av[v] * w.w;
                }
            }
        }
        __syncthreads();
    }
#pragma unroll
    for (int v = 0; v < 4; v++)
#pragma unroll
        for (int g = 0; g < 4; g++) {
            float4 r = make_float4(acc[v][g][0], acc[v][g][1], acc[v][g][2], acc[v][g][3]);
            *(float4*)&g_Wh[(size_t)(r0 + ty * 4 + v) * DV + g * 64 + tx * 4] = r;
        }
}

// ---------------------------------------------------------------------------
// Kernel 2: f = Wh @ a    (one warp per row)
// ---------------------------------------------------------------------------
__global__ __launch_bounds__(256) void k_f(const float* __restrict__ a) {
    const int warp = threadIdx.x >> 5, lane = threadIdx.x & 31;
    const int row = blockIdx.x * 8 + warp;
    const float4* wr = (const float4*)&g_Wh[(size_t)row * DV];
    const float4* a4 = (const float4*)a;
    float s = 0.f;
#pragma unroll
    for (int i = 0; i < 2; i++) {
        float4 w = wr[lane * 2 + i];
        float4 av = __ldg(&a4[lane * 2 + i]);
        s += w.x * av.x + w.y * av.y + w.z * av.z + w.w * av.w;
    }
#pragma unroll
    for (int off = 16; off; off >>= 1) s += __shfl_xor_sync(0xffffffffu, s, off);
    if (lane == 0) g_f[row] = s;
}

// ---------------------------------------------------------------------------
// Kernel 3 (pass A): per-row softmax stats m_i, 1/s_i over masked leaky scores
// Uniform formula: x = adj>0 ? leaky(f_i+f_j) : -1e9 (matches reference exactly,
// including fully-masked rows). 4 rows per block.
// ---------------------------------------------------------------------------
__global__ __launch_bounds__(256) void k_rowstats(const int* __restrict__ adj) {
    __shared__ float mS[256], sS[256];
    const int tid = threadIdx.x;
    for (int rr = 0; rr < 4; rr++) {
        const int row = blockIdx.x * 4 + rr;
        const float fi = g_f[row];
        const int4* ar = (const int4*)(adj + (size_t)row * NV);
        const float4* f4 = (const float4*)g_f;
        float m = -3.0e38f, s = 0.f;
#pragma unroll
        for (int q = 0; q < 8; q++) {
            int idx = q * 256 + tid;
            int4 ad = __ldg(&ar[idx]);
            float4 fj = __ldg(&f4[idx]);
            float x0 = ad.x > 0 ? lk(fi + fj.x) : NEGF;
            float x1 = ad.y > 0 ? lk(fi + fj.y) : NEGF;
            float x2 = ad.z > 0 ? lk(fi + fj.z) : NEGF;
            float x3 = ad.w > 0 ? lk(fi + fj.w) : NEGF;
            float mx = fmaxf(fmaxf(x0, x1), fmaxf(x2, x3));
            float nm = fmaxf(m, mx);
            s = s * __expf(m - nm) + __expf(x0 - nm) + __expf(x1 - nm)
              + __expf(x2 - nm) + __expf(x3 - nm);
            m = nm;
        }
        mS[tid] = m; sS[tid] = s;
        __syncthreads();
        for (int off = 128; off; off >>= 1) {
            if (tid < off) {
                float m1 = mS[tid], s1 = sS[tid];
                float m2 = mS[tid + off], s2 = sS[tid + off];
                float nm = fmaxf(m1, m2);
                mS[tid] = nm;
                sS[tid] = s1 * __expf(m1 - nm) + s2 * __expf(m2 - nm);
            }
            __syncthreads();
        }
        if (tid == 0) { g_m[row] = mS[0]; g_is[row] = 1.f / sS[0]; }
        __syncthreads();
    }
}

// ---------------------------------------------------------------------------
// Kernel 4 (pass B): per 64-row x 128-col output tile, loop K=8192 in steps
// of 32: recompute alpha tile in SMEM (write to gmem from col-block 0 only),
// then register-tiled fp32 MMA  h' += alpha_tile @ Wh_tile. Fused elu epilogue.
// grid = (2 col-halves, 128 row-tiles) = 256 blocks.
// ---------------------------------------------------------------------------
__global__ __launch_bounds__(256) void k_attn(const int* __restrict__ adj,
                                              float* __restrict__ out_elu,
                                              float* __restrict__ out_alpha) {
    __shared__ float aS[64][33];
    __shared__ float wS[32][128];
    __shared__ float frS[64], mSr[64], isS[64];
    const int tid = threadIdx.x;
    const int tx = tid & 15, ty = tid >> 4;
    const int r0 = blockIdx.y * 64;
    const int cb = blockIdx.x * 128;
    const bool writeA = (blockIdx.x == 0) && (out_alpha != nullptr);

    if (tid < 64) {
        frS[tid] = g_f[r0 + tid];
        mSr[tid] = g_m[r0 + tid];
        isS[tid] = g_is[r0 + tid];
    }
    float acc[4][2][4];
#pragma unroll
    for (int v = 0; v < 4; v++)
#pragma unroll
        for (int g = 0; g < 2; g++)
#pragma unroll
            for (int u = 0; u < 4; u++) acc[v][g][u] = 0.f;
    __syncthreads();

    for (int kb = 0; kb < NV; kb += 32) {
        // alpha tile 64x32: 512 int4 of adj
#pragma unroll
        for (int q = 0; q < 2; q++) {
            int lin = q * 256 + tid;
            int r = lin >> 3, c4 = (lin & 7) * 4;
            int4 ad = __ldg((const int4*)&adj[(size_t)(r0 + r) * NV + kb + c4]);
            float4 fj = __ldg((const float4*)&g_f[kb + c4]);
            float fi = frS[r], mm = mSr[r], is = isS[r];
            float4 al;
            al.x = __expf(((ad.x > 0) ? lk(fi + fj.x) : NEGF) - mm) * is;
            al.y = __expf(((ad.y > 0) ? lk(fi + fj.y) : NEGF) - mm) * is;
            al.z = __expf(((ad.z > 0) ? lk(fi + fj.z) : NEGF) - mm) * is;
            al.w = __expf(((ad.w > 0) ? lk(fi + fj.w) : NEGF) - mm) * is;
            aS[r][c4] = al.x; aS[r][c4 + 1] = al.y; aS[r][c4 + 2] = al.z; aS[r][c4 + 3] = al.w;
            if (writeA)
                *(float4*)&out_alpha[(size_t)(r0 + r) * NV + kb + c4] = al;
        }
        // Wh tile 32x128: 1024 float4 (L2-resident)
#pragma unroll
        for (int q = 0; q < 4; q++) {
            int lin = q * 256 + tid;
            int k = lin >> 5, c4 = (lin & 31) * 4;
            *(float4*)&wS[k][c4] = __ldg((const float4*)&g_Wh[(size_t)(kb + k) * DV + cb + c4]);
        }
        __syncthreads();
#pragma unroll 16
        for (int k = 0; k < 32; k++) {
            float av[4];
#pragma unroll
            for (int v = 0; v < 4; v++) av[v] = aS[ty * 4 + v][k];
            float4 w0 = *(float4*)&wS[k][tx * 4];
            float4 w1 = *(float4*)&wS[k][64 + tx * 4];
#pragma unroll
            for (int v = 0; v < 4; v++) {
                acc[v][0][0] += av[v] * w0.x;
                acc[v][0][1] += av[v] * w0.y;
                acc[v][0][2] += av[v] * w0.z;
                acc[v][0][3] += av[v] * w0.w;
                acc[v][1][0] += av[v] * w1.x;
                acc[v][1][1] += av[v] * w1.y;
                acc[v][1][2] += av[v] * w1.z;
                acc[v][1][3] += av[v] * w1.w;
            }
        }
        __syncthreads();
    }

    float* oe = out_elu ? out_elu : g_elu_scratch;
#pragma unroll
    for (int v = 0; v < 4; v++)
#pragma unroll
        for (int g = 0; g < 2; g++) {
            float4 r;
            r.x = elu_f(acc[v][g][0]);
            r.y = elu_f(acc[v][g][1]);
            r.z = elu_f(acc[v][g][2]);
            r.w = elu_f(acc[v][g][3]);
            *(float4*)&oe[(size_t)(r0 + ty * 4 + v) * DV + cb + g * 64 + tx * 4] = r;
        }
}

// ---------------------------------------------------------------------------
extern "C" void kernel_launch(void* const* d_in, const int* in_sizes, int n_in,
                              void* d_out, int out_size) {
    const float* h  = (const float*)d_in[0];
    const int*   adj = (const int*)d_in[1];
    const float* W  = (const float*)d_in[2];
    const float* a  = (const float*)d_in[3];
    float* out = (float*)d_out;

    const long long elu_n = (long long)NV * DV;       // 2,097,152
    const long long alp_n = (long long)NV * NV;       // 67,108,864

    float* out_elu;
    float* out_alpha;
    if ((long long)out_size >= elu_n + alp_n) {       // tuple concat: (elu, alpha)
        out_elu = out;
        out_alpha = out + elu_n;
    } else if ((long long)out_size == alp_n) {        // alpha only
        out_elu = nullptr;                            // kernel falls back to scratch
        out_alpha = out;
    } else {                                          // elu only
        out_elu = out;
        out_alpha = nullptr;
    }

    k_gemm_wh<<<NV / 64, 256>>>(h, W);
    k_f<<<NV / 8, 256>>>(a);
    k_rowstats<<<NV / 4, 256>>>(adj);
    dim3 gB(2, NV / 64);
    k_attn<<<gB, 256>>>(adj, out_elu, out_alpha);
}